// round 15
// baseline (speedup 1.0000x reference)
#include <cuda_runtime.h>
#include <cstdint>

// ---------------- problem constants (fixed by setup_inputs) ----------------
#define TOTAL   32768          // B*N nodes
#define BGRAPH  16
#define NPG     2048           // nodes per graph
#define CDIM    16
#define ODIM    64
#define KNN     16
#define NEDGE   (TOTAL*KNN)    // 524288

#define KTH     512            // knn threads per block
#define CHALF   1024           // candidates per knn thread
#define BUFD    8              // scan chunk size == slots per chunk

#define RB2     1024           // tail grid blocks (validated best)
#define NW2     (RB2*8)        // tail warps -> 4 nodes/warp

// ---------------- device scratch (static, allocation-free) -----------------
__device__ float g_u[TOTAL*ODIM];
__device__ float g_v[TOTAL*ODIM];
__device__ int   g_idx[NEDGE];
__device__ float g_gt[NEDGE];
__device__ float g_p1[RB2*ODIM];
__device__ float g_p2[RB2*ODIM];
__device__ float g_gp1[RB2];
__device__ float g_gp2[RB2];
__device__ float g_bnA[ODIM];
__device__ float g_bnB[ODIM];
__device__ float g_gAB[2];
__device__ unsigned g_sem1;
__device__ unsigned g_sem2;

__device__ __forceinline__ float silu_f(float z) {
    return __fdividef(z, 1.0f + __expf(-z));
}

__device__ __forceinline__ uint32_t smem_u32(const void* p) {
    uint32_t a;
    asm("{ .reg .u64 t; cvta.to.shared.u64 t, %1; cvt.u32.u64 %0, t; }"
        : "=r"(a) : "l"(p));
    return a;
}

__device__ __forceinline__ unsigned long long pk_f32x2(float lo, float hi) {
    unsigned long long r;
    asm("mov.b64 %0, {%1, %2};" : "=l"(r) : "f"(lo), "f"(hi));
    return r;
}
#define FMA2(d, a, b, c) asm("fma.rn.f32x2 %0, %1, %2, %3;" : "=l"(d) : "l"(a), "l"(b), "l"(c))
#define MUL2(d, a, b)    asm("mul.rn.f32x2 %0, %1, %2;"     : "=l"(d) : "l"(a), "l"(b))
#define ADD2(d, a, b)    asm("add.rn.f32x2 %0, %1, %2;"     : "=l"(d) : "l"(a), "l"(b))
#define UNPK2(lo, hi, v) asm("mov.b64 {%0, %1}, %2;" : "=f"(lo), "=f"(hi) : "l"(v))
#define LDSV2U64(a, b, addr) \
    asm volatile("ld.shared.v2.u64 {%0, %1}, [%2];" : "=l"(a), "=l"(b) : "r"(addr))

// Sorted-ascending sweep insert: buffer stays sorted, old max ejected.
__device__ __forceinline__ void ins16(float (&bk)[KNN], int (&bi)[KNN],
                                      float key, int jj) {
    float ck = key; int ci = jj;
#pragma unroll
    for (int p = 0; p < KNN; ++p) {
        float e = bk[p];  int ei = bi[p];
        bool sw = e > ck;
        bk[p] = fminf(e, ck);
        bi[p] = sw ? ci : ei;
        ck = fmaxf(e, ck);
        ci = sw ? ei : ci;
    }
}

__device__ __forceinline__ void knn_flush(float (&bk)[KNN], int (&bi)[KNN],
                                          unsigned pm,
                                          const unsigned long long* sbuf) {
    unsigned m = pm;
    while (m) {
        int t = __ffs(m) - 1;
        m &= m - 1;
        unsigned long long pk = sbuf[(unsigned)t*KTH + threadIdx.x];
        float key = __uint_as_float((unsigned)(pk >> 32));
        int jj = (int)(pk & 0xffffffffu);
        if (key < bk[KNN-1]) ins16(bk, bi, key, jj);
    }
}

// ---------------- kNN: 2 threads/query + halftime threshold exchange -------
__global__ void __launch_bounds__(KTH, 1) knn_kernel(const float* __restrict__ x) {
    extern __shared__ unsigned char smraw[];
    float4* sp4 = (float4*)smraw;                                   // 131072 B
    float*  ssq = (float*)(smraw + NPG*CDIM*4);                     // 8192 B
    unsigned long long* sbuf =
        (unsigned long long*)(smraw + NPG*CDIM*4 + NPG*4);          // 32768 B
    float* sthr = (float*)(smraw + NPG*CDIM*4 + NPG*4 + KTH*BUFD*8); // 2048 B

    int g = blockIdx.x >> 3;
    const float* xg = x + (size_t)g * (NPG*CDIM);
    int tid = threadIdx.x;

    for (int t = tid; t < NPG; t += KTH) {
        const float4* p = (const float4*)(xg + t*CDIM);
        float4 f0 = p[0], f1 = p[1], f2 = p[2], f3 = p[3];
        sp4[t*4+0] = f0; sp4[t*4+1] = f1; sp4[t*4+2] = f2; sp4[t*4+3] = f3;
        float sq = f0.x*f0.x + f0.y*f0.y + f0.z*f0.z + f0.w*f0.w
                 + f1.x*f1.x + f1.y*f1.y + f1.z*f1.z + f1.w*f1.w
                 + f2.x*f2.x + f2.y*f2.y + f2.z*f2.z + f2.w*f2.w
                 + f3.x*f3.x + f3.y*f3.y + f3.z*f3.z + f3.w*f3.w;
        ssq[t] = sq;
    }
    __syncthreads();

    int q  = tid & 255;
    int h  = tid >> 8;
    int qloc = ((blockIdx.x & 7) << 8) + q;

    float xq[16];
    ((float4*)xq)[0] = sp4[qloc*4+0];
    ((float4*)xq)[1] = sp4[qloc*4+1];
    ((float4*)xq)[2] = sp4[qloc*4+2];
    ((float4*)xq)[3] = sp4[qloc*4+3];
    unsigned long long xq2[8];
#pragma unroll
    for (int c = 0; c < 8; ++c)
        xq2[c] = pk_f32x2(-2.0f*xq[2*c], -2.0f*xq[2*c+1]);

    float bk[KNN]; int bi[KNN];
#pragma unroll
    for (int p = 0; p < KNN; ++p) { bk[p] = __int_as_float(0x7f800000); bi[p] = 0; }

    uint32_t tile_s = smem_u32(sp4);
    int jbase = h * CHALF;
    float othr = __int_as_float(0x7f800000);   // partner threshold (set at halftime)

    for (int half = 0; half < 2; ++half) {
        int j0 = half * (CHALF/2);
        int j1 = j0 + (CHALF/2);
        for (int jc = j0; jc < j1; jc += BUFD) {
            float4 sq4[2];
            const float4* sqp = (const float4*)(ssq + jbase + jc);
            sq4[0] = sqp[0]; sq4[1] = sqp[1];
            const float* sqf = (const float*)sq4;

            uint32_t cbase = tile_s + (uint32_t)(jbase + jc) * 64u;
            float cmax = fminf(bk[KNN-1], othr);
            unsigned pm = 0;
#pragma unroll
            for (int t = 0; t < BUFD; ++t) {
                uint32_t addr = cbase + (uint32_t)t * 64u;
                unsigned long long c0, c1, c2, c3, c4, c5, c6, c7;
                LDSV2U64(c0, c1, addr);
                LDSV2U64(c2, c3, addr + 16u);
                LDSV2U64(c4, c5, addr + 32u);
                LDSV2U64(c6, c7, addr + 48u);
                unsigned long long accA, accB;
                MUL2(accA, xq2[0], c0);
                FMA2(accA, xq2[1], c1, accA);
                FMA2(accA, xq2[2], c2, accA);
                FMA2(accA, xq2[3], c3, accA);
                MUL2(accB, xq2[4], c4);
                FMA2(accB, xq2[5], c5, accB);
                FMA2(accB, xq2[6], c6, accB);
                FMA2(accB, xq2[7], c7, accB);
                ADD2(accA, accA, accB);
                float lo, hi;
                UNPK2(lo, hi, accA);
                float key = (sqf[t] + lo) + hi;

                bool push = (key < cmax);
                if (push) {
                    sbuf[t*(unsigned)KTH + tid] =
                        (((unsigned long long)__float_as_uint(key)) << 32)
                        | (unsigned)(jbase + jc + t);
                }
                pm |= push ? (1u << t) : 0u;
            }
            if (__any_sync(0xffffffffu, pm != 0u)) {
                knn_flush(bk, bi, pm, sbuf);
            }
        }
        if (half == 0) {
            // one-shot threshold exchange with the co-thread
            sthr[tid] = bk[KNN-1];
            __syncthreads();
            othr = sthr[tid ^ 256];
        }
    }

    // Final merge: reuse sp4 (scan complete) as a 512x16 u64 exchange area.
    __syncthreads();
    unsigned long long* xchg = (unsigned long long*)sp4;   // 64 KB used of 131 KB
#pragma unroll
    for (int p = 0; p < KNN; ++p) {
        xchg[p*(unsigned)KTH + tid] =
            (((unsigned long long)__float_as_uint(bk[p])) << 32) | (unsigned)bi[p];
    }
    __syncthreads();
    if (h == 0) {
#pragma unroll
        for (int p = 0; p < KNN; ++p) {
            unsigned long long pk = xchg[p*(unsigned)KTH + tid + 256];
            float key = __uint_as_float((unsigned)(pk >> 32));
            int jj = (int)(pk & 0xffffffffu);
            if (key < bk[KNN-1]) ins16(bk, bi, key, jj);
        }
        int goff = g * NPG;
        int4* op = (int4*)(g_idx + (size_t)(g*NPG + qloc) * KNN);
#pragma unroll
        for (int p = 0; p < 4; ++p) {
            op[p] = make_int4(goff + bi[4*p], goff + bi[4*p+1],
                              goff + bi[4*p+2], goff + bi[4*p+3]);
        }
    }
}

// ---------------- u/v per node: h_edge = u_i + v_j -------------------------
__global__ void uv_kernel(const float* __restrict__ x,
                          const float* __restrict__ W1,
                          const float* __restrict__ b1) {
    __shared__ float sW[2*CDIM*ODIM];
    for (int i = threadIdx.x; i < 2*CDIM*ODIM; i += blockDim.x) sW[i] = W1[i];
    __syncthreads();
    int gid = blockIdx.x * blockDim.x + threadIdx.x;
    int node = gid >> 6;
    int o = gid & 63;
    const float4* xp = (const float4*)(x + (size_t)node * CDIM);
    float xc[16];
    ((float4*)xc)[0] = xp[0];
    ((float4*)xc)[1] = xp[1];
    ((float4*)xc)[2] = xp[2];
    ((float4*)xc)[3] = xp[3];
    float u = b1[o], v = 0.f;
#pragma unroll
    for (int c = 0; c < 16; ++c) {
        float wt = sW[c*ODIM + o];
        float wb = sW[(c+16)*ODIM + o];
        u = fmaf(xc[c], wt - wb, u);
        v = fmaf(xc[c], wb, v);
    }
    g_u[gid] = u;
    g_v[gid] = v;
}

// ---------------- BN stats over edges + last-block finalize ----------------
__global__ void __launch_bounds__(256) hstat_kernel(const float* __restrict__ g1,
                                                    const float* __restrict__ be1) {
    int tid = threadIdx.x;
    int gw = (blockIdx.x * 256 + tid) >> 5;
    int l = tid & 31;
    int wl = tid >> 5;

    float s10 = 0.f, s11 = 0.f, s20 = 0.f, s21 = 0.f;
    for (int node = gw; node < TOTAL; node += NW2) {
        float u0 = g_u[node*ODIM + l];
        float u1 = g_u[node*ODIM + 32 + l];
        const int4* ip4 = (const int4*)(g_idx + node*KNN);
        int4 i0 = ip4[0], i1 = ip4[1], i2 = ip4[2], i3 = ip4[3];
        int jj[16] = {i0.x,i0.y,i0.z,i0.w, i1.x,i1.y,i1.z,i1.w,
                      i2.x,i2.y,i2.z,i2.w, i3.x,i3.y,i3.z,i3.w};
#pragma unroll
        for (int k = 0; k < KNN; ++k) {
            int j = jj[k];
            float v0 = g_v[j*ODIM + l];
            float v1 = g_v[j*ODIM + 32 + l];
            float h0 = u0 + v0, h1 = u1 + v1;
            s10 += h0; s20 = fmaf(h0, h0, s20);
            s11 += h1; s21 = fmaf(h1, h1, s21);
        }
    }
    __shared__ float sh1[8][64];
    __shared__ float sh2[8][64];
    sh1[wl][l] = s10; sh1[wl][l+32] = s11;
    sh2[wl][l] = s20; sh2[wl][l+32] = s21;
    __syncthreads();
    if (tid < 64) {
        float p1 = 0.f, p2 = 0.f;
#pragma unroll
        for (int w = 0; w < 8; ++w) { p1 += sh1[w][tid]; p2 += sh2[w][tid]; }
        g_p1[blockIdx.x*ODIM + tid] = p1;
        g_p2[blockIdx.x*ODIM + tid] = p2;
    }
    // last-block deterministic finalize
    __shared__ bool last;
    __threadfence();
    __syncthreads();
    if (tid == 0) {
        unsigned t = atomicAdd(&g_sem1, 1);
        last = (t == RB2 - 1);
        if (last) g_sem1 = 0;
    }
    __syncthreads();
    if (last) {
        int o   = tid & 63;
        int grp = tid >> 6;   // 0..3
        float s1 = 0.f, s2 = 0.f;
        for (int b = grp; b < RB2; b += 4) {
            s1 += g_p1[b*ODIM + o];
            s2 += g_p2[b*ODIM + o];
        }
        sh1[grp][o] = s1; sh2[grp][o] = s2;
        __syncthreads();
        if (tid < 64) {
            float p1 = 0.f, p2 = 0.f;
#pragma unroll
            for (int w = 0; w < 4; ++w) { p1 += sh1[w][tid]; p2 += sh2[w][tid]; }
            const float invE = 1.0f / (float)NEDGE;
            float mu  = p1 * invE;
            float var = p2 * invE - mu*mu;
            float inv = rsqrtf(var + 1e-5f);
            float A = g1[tid] * inv;
            g_bnA[tid] = A;
            g_bnB[tid] = fmaf(-mu, A, be1[tid]);
        }
    }
}

// ---------------- gate: gt per edge (paired reduce) + finalize -------------
__global__ void __launch_bounds__(256) gate_kernel(const float* __restrict__ Wg,
                                                   const float* __restrict__ bgp,
                                                   const float* __restrict__ gg,
                                                   const float* __restrict__ beg) {
    int tid = threadIdx.x;
    int gw = (blockIdx.x * 256 + tid) >> 5;
    int l = tid & 31;
    int wl = tid >> 5;
    float A0 = g_bnA[l], B0 = g_bnB[l], A1 = g_bnA[l+32], B1 = g_bnB[l+32];
    float w0 = Wg[l], w1 = Wg[l+32];
    float bgs = bgp[0];
    bool hi16 = (l & 16) != 0;
    float gs = 0.f, gss = 0.f;
    for (int node = gw; node < TOTAL; node += NW2) {
        float u0 = g_u[node*ODIM + l], u1 = g_u[node*ODIM + 32 + l];
        const int4* ip4 = (const int4*)(g_idx + node*KNN);
        int4 i0 = ip4[0], i1 = ip4[1], i2 = ip4[2], i3 = ip4[3];
        int jj[16] = {i0.x,i0.y,i0.z,i0.w, i1.x,i1.y,i1.z,i1.w,
                      i2.x,i2.y,i2.z,i2.w, i3.x,i3.y,i3.z,i3.w};
#pragma unroll
        for (int k = 0; k < KNN; k += 2) {
            int ja = jj[k], jb = jj[k+1];
            float va0 = g_v[ja*ODIM + l], va1 = g_v[ja*ODIM + 32 + l];
            float vb0 = g_v[jb*ODIM + l], vb1 = g_v[jb*ODIM + 32 + l];
            float pa = fmaf(silu_f(fmaf(u0 + va0, A0, B0)), w0,
                            silu_f(fmaf(u1 + va1, A1, B1)) * w1);
            float pb = fmaf(silu_f(fmaf(u0 + vb0, A0, B0)), w0,
                            silu_f(fmaf(u1 + vb1, A1, B1)) * w1);
            float xx = hi16 ? pb : pa;
            float yv = hi16 ? pa : pb;
            float s  = xx + __shfl_xor_sync(0xffffffffu, yv, 16);
#pragma unroll
            for (int off = 8; off > 0; off >>= 1)
                s += __shfl_xor_sync(0xffffffffu, s, off);
            float gta = s + bgs;
            if (l == 0)  g_gt[node*KNN + k]     = gta;
            if (l == 16) g_gt[node*KNN + k + 1] = gta;
            float gtb = __shfl_sync(0xffffffffu, gta, 16);
            gs += gta; gss = fmaf(gta, gta, gss);
            gs += gtb; gss = fmaf(gtb, gtb, gss);
        }
    }
    __shared__ float sg1[8], sg2[8];
    if (l == 0) { sg1[wl] = gs; sg2[wl] = gss; }
    __syncthreads();
    if (tid == 0) {
        float a = 0.f, b2 = 0.f;
#pragma unroll
        for (int w = 0; w < 8; ++w) { a += sg1[w]; b2 += sg2[w]; }
        g_gp1[blockIdx.x] = a; g_gp2[blockIdx.x] = b2;
    }
    // last-block deterministic finalize
    __shared__ bool last;
    __threadfence();
    __syncthreads();
    if (tid == 0) {
        unsigned t = atomicAdd(&g_sem2, 1);
        last = (t == RB2 - 1);
        if (last) g_sem2 = 0;
    }
    __syncthreads();
    if (last) {
        float a  = g_gp1[tid] + g_gp1[tid + 256] + g_gp1[tid + 512] + g_gp1[tid + 768];
        float b2 = g_gp2[tid] + g_gp2[tid + 256] + g_gp2[tid + 512] + g_gp2[tid + 768];
#pragma unroll
        for (int off = 16; off > 0; off >>= 1) {
            a  += __shfl_xor_sync(0xffffffffu, a,  off);
            b2 += __shfl_xor_sync(0xffffffffu, b2, off);
        }
        __shared__ float sa[8], sb[8];
        if (l == 0) { sa[wl] = a; sb[wl] = b2; }
        __syncthreads();
        if (tid == 0) {
            float s1 = 0.f, s2 = 0.f;
#pragma unroll
            for (int w = 0; w < 8; ++w) { s1 += sa[w]; s2 += sb[w]; }
            const float invE = 1.0f / (float)NEDGE;
            float mu  = s1 * invE;
            float var = s2 * invE - mu*mu;
            float inv = rsqrtf(var + 1e-5f);
            float A = gg[0] * inv;
            g_gAB[0] = A;
            g_gAB[1] = fmaf(-mu, A, beg[0]);
        }
    }
}

// ---------------- out: softmax over K + recompute hn from v gathers --------
__global__ void __launch_bounds__(256) out_kernel(float* __restrict__ out) {
    int tid = threadIdx.x;
    int gw = (blockIdx.x * 256 + tid) >> 5;
    int l = tid & 31;
    float A0 = g_bnA[l], B0 = g_bnB[l], A1 = g_bnA[l+32], B1 = g_bnB[l+32];
    float gA = g_gAB[0], gB = g_gAB[1];
    for (int node = gw; node < TOTAL; node += NW2) {
        float gt = (l < 16) ? g_gt[node*KNN + l] : 0.f;
        float z = fmaf(gt, gA, gB);
        float s = silu_f(z);
        float sm = (l < 16) ? s : -1e30f;
#pragma unroll
        for (int off = 16; off > 0; off >>= 1)
            sm = fmaxf(sm, __shfl_xor_sync(0xffffffffu, sm, off));
        float e = (l < 16) ? __expf(s - sm) : 0.f;
        float tot = e;
#pragma unroll
        for (int off = 16; off > 0; off >>= 1)
            tot += __shfl_xor_sync(0xffffffffu, tot, off);
        float a = __fdividef(e, tot);

        float u0 = g_u[node*ODIM + l], u1 = g_u[node*ODIM + 32 + l];
        const int4* ip4 = (const int4*)(g_idx + node*KNN);
        int4 i0 = ip4[0], i1 = ip4[1], i2 = ip4[2], i3 = ip4[3];
        int jj[16] = {i0.x,i0.y,i0.z,i0.w, i1.x,i1.y,i1.z,i1.w,
                      i2.x,i2.y,i2.z,i2.w, i3.x,i3.y,i3.z,i3.w};
        float acc0 = 0.f, acc1 = 0.f;
#pragma unroll
        for (int k = 0; k < KNN; ++k) {
            float ak = __shfl_sync(0xffffffffu, a, k);
            int j = jj[k];
            float v0 = g_v[j*ODIM + l], v1 = g_v[j*ODIM + 32 + l];
            float hn0 = silu_f(fmaf(u0 + v0, A0, B0));
            float hn1 = silu_f(fmaf(u1 + v1, A1, B1));
            acc0 = fmaf(ak, hn0, acc0);
            acc1 = fmaf(ak, hn1, acc1);
        }
        out[node*ODIM + l] = acc0;
        out[node*ODIM + 32 + l] = acc1;
    }
}

// ---------------- launch ----------------------------------------------------
extern "C" void kernel_launch(void* const* d_in, const int* in_sizes, int n_in,
                              void* d_out, int out_size) {
    const float* x   = (const float*)d_in[0];
    const float* W1  = (const float*)d_in[2];
    const float* b1  = (const float*)d_in[3];
    const float* g1  = (const float*)d_in[4];
    const float* be1 = (const float*)d_in[5];
    const float* Wg  = (const float*)d_in[6];
    const float* bg  = (const float*)d_in[7];
    const float* gg  = (const float*)d_in[8];
    const float* beg = (const float*)d_in[9];
    float* out = (float*)d_out;

    const int knn_smem = NPG*CDIM*4 + NPG*4 + KTH*BUFD*8 + KTH*4;  // 174080 B
    cudaFuncSetAttribute(knn_kernel, cudaFuncAttributeMaxDynamicSharedMemorySize, knn_smem);

    uv_kernel<<<(TOTAL*ODIM)/256, 256>>>(x, W1, b1);       // 1
    knn_kernel<<<BGRAPH*(NPG/256), KTH, knn_smem>>>(x);    // 2
    hstat_kernel<<<RB2, 256>>>(g1, be1);                   // 3 (+ BN finalize)
    gate_kernel<<<RB2, 256>>>(Wg, bg, gg, beg);            // 4 (+ gate finalize) <- ncu
    out_kernel<<<RB2, 256>>>(out);                         // 5
}

// round 16
// speedup vs baseline: 1.0672x; 1.0672x over previous
#include <cuda_runtime.h>
#include <cstdint>

// ---------------- problem constants (fixed by setup_inputs) ----------------
#define TOTAL   32768          // B*N nodes
#define BGRAPH  16
#define NPG     2048           // nodes per graph
#define CDIM    16
#define ODIM    64
#define KNN     16
#define NEDGE   (TOTAL*KNN)    // 524288

#define KTH     512            // knn threads per block
#define CHALF   1024           // candidates per knn thread
#define BUFD    16             // scan chunk size == slots per chunk (R13 config)

#define RB2     1024           // tail grid blocks (validated best)
#define NW2     (RB2*8)        // tail warps -> 4 nodes/warp

// ---------------- device scratch (static, allocation-free) -----------------
__device__ float g_u[TOTAL*ODIM];
__device__ float g_v[TOTAL*ODIM];
__device__ int   g_idx[NEDGE];
__device__ float g_gt[NEDGE];
__device__ float g_p1[RB2*ODIM];
__device__ float g_p2[RB2*ODIM];
__device__ float g_gp1[RB2];
__device__ float g_gp2[RB2];
__device__ float g_bnA[ODIM];
__device__ float g_bnB[ODIM];
__device__ float g_gAB[2];
__device__ unsigned g_sem1;
__device__ unsigned g_sem2;

__device__ __forceinline__ float silu_f(float z) {
    return __fdividef(z, 1.0f + __expf(-z));
}

__device__ __forceinline__ uint32_t smem_u32(const void* p) {
    uint32_t a;
    asm("{ .reg .u64 t; cvta.to.shared.u64 t, %1; cvt.u32.u64 %0, t; }"
        : "=r"(a) : "l"(p));
    return a;
}

__device__ __forceinline__ unsigned long long pk_f32x2(float lo, float hi) {
    unsigned long long r;
    asm("mov.b64 %0, {%1, %2};" : "=l"(r) : "f"(lo), "f"(hi));
    return r;
}
#define FMA2(d, a, b, c) asm("fma.rn.f32x2 %0, %1, %2, %3;" : "=l"(d) : "l"(a), "l"(b), "l"(c))
#define MUL2(d, a, b)    asm("mul.rn.f32x2 %0, %1, %2;"     : "=l"(d) : "l"(a), "l"(b))
#define ADD2(d, a, b)    asm("add.rn.f32x2 %0, %1, %2;"     : "=l"(d) : "l"(a), "l"(b))
#define UNPK2(lo, hi, v) asm("mov.b64 {%0, %1}, %2;" : "=f"(lo), "=f"(hi) : "l"(v))
#define LDSV2U64(a, b, addr) \
    asm volatile("ld.shared.v2.u64 {%0, %1}, [%2];" : "=l"(a), "=l"(b) : "r"(addr))

// Sorted-ascending sweep insert: buffer stays sorted, old max ejected.
__device__ __forceinline__ void ins16(float (&bk)[KNN], int (&bi)[KNN],
                                      float key, int jj) {
    float ck = key; int ci = jj;
#pragma unroll
    for (int p = 0; p < KNN; ++p) {
        float e = bk[p];  int ei = bi[p];
        bool sw = e > ck;
        bk[p] = fminf(e, ck);
        bi[p] = sw ? ci : ei;
        ck = fmaxf(e, ck);
        ci = sw ? ei : ci;
    }
}

__device__ __forceinline__ void knn_flush(float (&bk)[KNN], int (&bi)[KNN],
                                          unsigned pm,
                                          const unsigned long long* sbuf) {
    unsigned m = pm;
    while (m) {
        int t = __ffs(m) - 1;
        m &= m - 1;
        unsigned long long pk = sbuf[(unsigned)t*KTH + threadIdx.x];
        float key = __uint_as_float((unsigned)(pk >> 32));
        int jj = (int)(pk & 0xffffffffu);
        if (key < bk[KNN-1]) ins16(bk, bi, key, jj);
    }
}

// ---------------- kNN (+fused u/v): 2 threads per query --------------------
// smem: sp4 131072 | ssq 8192 | sbuf 65536 | sW 8192 | sb1 256  = 213248 B
__global__ void __launch_bounds__(KTH, 1) knn_kernel(const float* __restrict__ x,
                                                     const float* __restrict__ W1,
                                                     const float* __restrict__ b1) {
    extern __shared__ unsigned char smraw[];
    float4* sp4 = (float4*)smraw;
    float*  ssq = (float*)(smraw + NPG*CDIM*4);
    unsigned long long* sbuf =
        (unsigned long long*)(smraw + NPG*CDIM*4 + NPG*4);
    float* sW  = (float*)(smraw + NPG*CDIM*4 + NPG*4 + KTH*BUFD*8);
    float* sb1 = (float*)(smraw + NPG*CDIM*4 + NPG*4 + KTH*BUFD*8 + 2*CDIM*ODIM*4);

    int g = blockIdx.x >> 3;
    const float* xg = x + (size_t)g * (NPG*CDIM);
    int tid = threadIdx.x;

    for (int t = tid; t < NPG; t += KTH) {
        const float4* p = (const float4*)(xg + t*CDIM);
        float4 f0 = p[0], f1 = p[1], f2 = p[2], f3 = p[3];
        sp4[t*4+0] = f0; sp4[t*4+1] = f1; sp4[t*4+2] = f2; sp4[t*4+3] = f3;
        float sq = f0.x*f0.x + f0.y*f0.y + f0.z*f0.z + f0.w*f0.w
                 + f1.x*f1.x + f1.y*f1.y + f1.z*f1.z + f1.w*f1.w
                 + f2.x*f2.x + f2.y*f2.y + f2.z*f2.z + f2.w*f2.w
                 + f3.x*f3.x + f3.y*f3.y + f3.z*f3.z + f3.w*f3.w;
        ssq[t] = sq;
    }
    for (int i = tid; i < 2*CDIM*ODIM; i += KTH) sW[i] = W1[i];
    if (tid < ODIM) sb1[tid] = b1[tid];
    __syncthreads();

    int q  = tid & 255;
    int h  = tid >> 8;
    int qloc = ((blockIdx.x & 7) << 8) + q;

    float xq[16];
    ((float4*)xq)[0] = sp4[qloc*4+0];
    ((float4*)xq)[1] = sp4[qloc*4+1];
    ((float4*)xq)[2] = sp4[qloc*4+2];
    ((float4*)xq)[3] = sp4[qloc*4+3];

    // ---- fused u/v: this thread handles channels [h*32, h*32+32) ----
    {
        int node = g * NPG + qloc;
        float uo[32], vo[32];
#pragma unroll
        for (int oo = 0; oo < 32; ++oo) {
            int o = h * 32 + oo;
            float u = sb1[o], v = 0.f;
#pragma unroll
            for (int c = 0; c < 16; ++c) {
                float wt = sW[c*ODIM + o];
                float wb = sW[(c+16)*ODIM + o];
                u = fmaf(xq[c], wt - wb, u);
                v = fmaf(xq[c], wb, v);
            }
            uo[oo] = u; vo[oo] = v;
        }
        float4* up = (float4*)(g_u + (size_t)node*ODIM + h*32);
        float4* vp = (float4*)(g_v + (size_t)node*ODIM + h*32);
#pragma unroll
        for (int o4 = 0; o4 < 8; ++o4) {
            up[o4] = ((float4*)uo)[o4];
            vp[o4] = ((float4*)vo)[o4];
        }
    }

#pragma unroll
    for (int c = 0; c < 16; ++c) xq[c] *= -2.0f;   // key = sq_j - 2*dot

    float bk[KNN]; int bi[KNN];
#pragma unroll
    for (int p = 0; p < KNN; ++p) { bk[p] = __int_as_float(0x7f800000); bi[p] = 0; }
    unsigned long long xq2[8];
#pragma unroll
    for (int c = 0; c < 8; ++c)
        xq2[c] = pk_f32x2(xq[2*c], xq[2*c+1]);

    uint32_t tile_s = smem_u32(sp4);
    int jbase = h * CHALF;

    for (int jc = 0; jc < CHALF; jc += BUFD) {
        float4 sq4[4];
        const float4* sqp = (const float4*)(ssq + jbase + jc);
        sq4[0] = sqp[0]; sq4[1] = sqp[1]; sq4[2] = sqp[2]; sq4[3] = sqp[3];
        const float* sqf = (const float*)sq4;

        uint32_t cbase = tile_s + (uint32_t)(jbase + jc) * 64u;
        float cmax = bk[KNN-1];
        unsigned pm = 0;
#pragma unroll
        for (int t = 0; t < BUFD; ++t) {
            uint32_t addr = cbase + (uint32_t)t * 64u;
            unsigned long long c0, c1, c2, c3, c4, c5, c6, c7;
            LDSV2U64(c0, c1, addr);
            LDSV2U64(c2, c3, addr + 16u);
            LDSV2U64(c4, c5, addr + 32u);
            LDSV2U64(c6, c7, addr + 48u);
            unsigned long long accA, accB;
            MUL2(accA, xq2[0], c0);
            FMA2(accA, xq2[1], c1, accA);
            FMA2(accA, xq2[2], c2, accA);
            FMA2(accA, xq2[3], c3, accA);
            MUL2(accB, xq2[4], c4);
            FMA2(accB, xq2[5], c5, accB);
            FMA2(accB, xq2[6], c6, accB);
            FMA2(accB, xq2[7], c7, accB);
            ADD2(accA, accA, accB);
            float lo, hi;
            UNPK2(lo, hi, accA);
            float key = (sqf[t] + lo) + hi;

            bool push = (key < cmax);
            if (push) {
                sbuf[t*(unsigned)KTH + tid] =
                    (((unsigned long long)__float_as_uint(key)) << 32)
                    | (unsigned)(jbase + jc + t);
            }
            pm |= push ? (1u << t) : 0u;
        }
        if (__any_sync(0xffffffffu, pm != 0u)) {
            knn_flush(bk, bi, pm, sbuf);
        }
    }

    __syncthreads();
#pragma unroll
    for (int p = 0; p < KNN; ++p) {
        sbuf[p*(unsigned)KTH + tid] =
            (((unsigned long long)__float_as_uint(bk[p])) << 32) | (unsigned)bi[p];
    }
    __syncthreads();
    if (h == 0) {
#pragma unroll
        for (int p = 0; p < KNN; ++p) {
            unsigned long long pk = sbuf[p*(unsigned)KTH + tid + 256];
            float key = __uint_as_float((unsigned)(pk >> 32));
            int jj = (int)(pk & 0xffffffffu);
            if (key < bk[KNN-1]) ins16(bk, bi, key, jj);
        }
        int goff = g * NPG;
        int4* op = (int4*)(g_idx + (size_t)(g*NPG + qloc) * KNN);
#pragma unroll
        for (int p = 0; p < 4; ++p) {
            op[p] = make_int4(goff + bi[4*p], goff + bi[4*p+1],
                              goff + bi[4*p+2], goff + bi[4*p+3]);
        }
    }
}

// ---------------- BN stats over edges + last-block finalize ----------------
__global__ void __launch_bounds__(256) hstat_kernel(const float* __restrict__ g1,
                                                    const float* __restrict__ be1) {
    int tid = threadIdx.x;
    int gw = (blockIdx.x * 256 + tid) >> 5;
    int l = tid & 31;
    int wl = tid >> 5;

    float s10 = 0.f, s11 = 0.f, s20 = 0.f, s21 = 0.f;
    for (int node = gw; node < TOTAL; node += NW2) {
        float u0 = g_u[node*ODIM + l];
        float u1 = g_u[node*ODIM + 32 + l];
        const int4* ip4 = (const int4*)(g_idx + node*KNN);
        int4 i0 = ip4[0], i1 = ip4[1], i2 = ip4[2], i3 = ip4[3];
        int jj[16] = {i0.x,i0.y,i0.z,i0.w, i1.x,i1.y,i1.z,i1.w,
                      i2.x,i2.y,i2.z,i2.w, i3.x,i3.y,i3.z,i3.w};
#pragma unroll
        for (int k = 0; k < KNN; ++k) {
            int j = jj[k];
            float v0 = g_v[j*ODIM + l];
            float v1 = g_v[j*ODIM + 32 + l];
            float h0 = u0 + v0, h1 = u1 + v1;
            s10 += h0; s20 = fmaf(h0, h0, s20);
            s11 += h1; s21 = fmaf(h1, h1, s21);
        }
    }
    __shared__ float sh1[8][64];
    __shared__ float sh2[8][64];
    sh1[wl][l] = s10; sh1[wl][l+32] = s11;
    sh2[wl][l] = s20; sh2[wl][l+32] = s21;
    __syncthreads();
    if (tid < 64) {
        float p1 = 0.f, p2 = 0.f;
#pragma unroll
        for (int w = 0; w < 8; ++w) { p1 += sh1[w][tid]; p2 += sh2[w][tid]; }
        g_p1[blockIdx.x*ODIM + tid] = p1;
        g_p2[blockIdx.x*ODIM + tid] = p2;
    }
    // last-block deterministic finalize
    __shared__ bool last;
    __threadfence();
    __syncthreads();
    if (tid == 0) {
        unsigned t = atomicAdd(&g_sem1, 1);
        last = (t == RB2 - 1);
        if (last) g_sem1 = 0;
    }
    __syncthreads();
    if (last) {
        int o   = tid & 63;
        int grp = tid >> 6;   // 0..3
        float s1 = 0.f, s2 = 0.f;
        for (int b = grp; b < RB2; b += 4) {
            s1 += g_p1[b*ODIM + o];
            s2 += g_p2[b*ODIM + o];
        }
        sh1[grp][o] = s1; sh2[grp][o] = s2;
        __syncthreads();
        if (tid < 64) {
            float p1 = 0.f, p2 = 0.f;
#pragma unroll
            for (int w = 0; w < 4; ++w) { p1 += sh1[w][tid]; p2 += sh2[w][tid]; }
            const float invE = 1.0f / (float)NEDGE;
            float mu  = p1 * invE;
            float var = p2 * invE - mu*mu;
            float inv = rsqrtf(var + 1e-5f);
            float A = g1[tid] * inv;
            g_bnA[tid] = A;
            g_bnB[tid] = fmaf(-mu, A, be1[tid]);
        }
    }
}

// ---------------- gate: gt per edge (paired reduce) + finalize -------------
__global__ void __launch_bounds__(256) gate_kernel(const float* __restrict__ Wg,
                                                   const float* __restrict__ bgp,
                                                   const float* __restrict__ gg,
                                                   const float* __restrict__ beg) {
    int tid = threadIdx.x;
    int gw = (blockIdx.x * 256 + tid) >> 5;
    int l = tid & 31;
    int wl = tid >> 5;
    float A0 = g_bnA[l], B0 = g_bnB[l], A1 = g_bnA[l+32], B1 = g_bnB[l+32];
    float w0 = Wg[l], w1 = Wg[l+32];
    float bgs = bgp[0];
    bool hi16 = (l & 16) != 0;
    float gs = 0.f, gss = 0.f;
    for (int node = gw; node < TOTAL; node += NW2) {
        float u0 = g_u[node*ODIM + l], u1 = g_u[node*ODIM + 32 + l];
        const int4* ip4 = (const int4*)(g_idx + node*KNN);
        int4 i0 = ip4[0], i1 = ip4[1], i2 = ip4[2], i3 = ip4[3];
        int jj[16] = {i0.x,i0.y,i0.z,i0.w, i1.x,i1.y,i1.z,i1.w,
                      i2.x,i2.y,i2.z,i2.w, i3.x,i3.y,i3.z,i3.w};
#pragma unroll
        for (int k = 0; k < KNN; k += 2) {
            int ja = jj[k], jb = jj[k+1];
            float va0 = g_v[ja*ODIM + l], va1 = g_v[ja*ODIM + 32 + l];
            float vb0 = g_v[jb*ODIM + l], vb1 = g_v[jb*ODIM + 32 + l];
            float pa = fmaf(silu_f(fmaf(u0 + va0, A0, B0)), w0,
                            silu_f(fmaf(u1 + va1, A1, B1)) * w1);
            float pb = fmaf(silu_f(fmaf(u0 + vb0, A0, B0)), w0,
                            silu_f(fmaf(u1 + vb1, A1, B1)) * w1);
            float xx = hi16 ? pb : pa;
            float yv = hi16 ? pa : pb;
            float s  = xx + __shfl_xor_sync(0xffffffffu, yv, 16);
#pragma unroll
            for (int off = 8; off > 0; off >>= 1)
                s += __shfl_xor_sync(0xffffffffu, s, off);
            float gta = s + bgs;
            if (l == 0)  g_gt[node*KNN + k]     = gta;
            if (l == 16) g_gt[node*KNN + k + 1] = gta;
            float gtb = __shfl_sync(0xffffffffu, gta, 16);
            gs += gta; gss = fmaf(gta, gta, gss);
            gs += gtb; gss = fmaf(gtb, gtb, gss);
        }
    }
    __shared__ float sg1[8], sg2[8];
    if (l == 0) { sg1[wl] = gs; sg2[wl] = gss; }
    __syncthreads();
    if (tid == 0) {
        float a = 0.f, b2 = 0.f;
#pragma unroll
        for (int w = 0; w < 8; ++w) { a += sg1[w]; b2 += sg2[w]; }
        g_gp1[blockIdx.x] = a; g_gp2[blockIdx.x] = b2;
    }
    // last-block deterministic finalize
    __shared__ bool last;
    __threadfence();
    __syncthreads();
    if (tid == 0) {
        unsigned t = atomicAdd(&g_sem2, 1);
        last = (t == RB2 - 1);
        if (last) g_sem2 = 0;
    }
    __syncthreads();
    if (last) {
        float a  = g_gp1[tid] + g_gp1[tid + 256] + g_gp1[tid + 512] + g_gp1[tid + 768];
        float b2 = g_gp2[tid] + g_gp2[tid + 256] + g_gp2[tid + 512] + g_gp2[tid + 768];
#pragma unroll
        for (int off = 16; off > 0; off >>= 1) {
            a  += __shfl_xor_sync(0xffffffffu, a,  off);
            b2 += __shfl_xor_sync(0xffffffffu, b2, off);
        }
        __shared__ float sa[8], sb[8];
        if (l == 0) { sa[wl] = a; sb[wl] = b2; }
        __syncthreads();
        if (tid == 0) {
            float s1 = 0.f, s2 = 0.f;
#pragma unroll
            for (int w = 0; w < 8; ++w) { s1 += sa[w]; s2 += sb[w]; }
            const float invE = 1.0f / (float)NEDGE;
            float mu  = s1 * invE;
            float var = s2 * invE - mu*mu;
            float inv = rsqrtf(var + 1e-5f);
            float A = gg[0] * inv;
            g_gAB[0] = A;
            g_gAB[1] = fmaf(-mu, A, beg[0]);
        }
    }
}

// ---------------- out: softmax over K + recompute hn from v gathers --------
__global__ void __launch_bounds__(256) out_kernel(float* __restrict__ out) {
    int tid = threadIdx.x;
    int gw = (blockIdx.x * 256 + tid) >> 5;
    int l = tid & 31;
    float A0 = g_bnA[l], B0 = g_bnB[l], A1 = g_bnA[l+32], B1 = g_bnB[l+32];
    float gA = g_gAB[0], gB = g_gAB[1];
    for (int node = gw; node < TOTAL; node += NW2) {
        float gt = (l < 16) ? g_gt[node*KNN + l] : 0.f;
        float z = fmaf(gt, gA, gB);
        float s = silu_f(z);
        float sm = (l < 16) ? s : -1e30f;
#pragma unroll
        for (int off = 16; off > 0; off >>= 1)
            sm = fmaxf(sm, __shfl_xor_sync(0xffffffffu, sm, off));
        float e = (l < 16) ? __expf(s - sm) : 0.f;
        float tot = e;
#pragma unroll
        for (int off = 16; off > 0; off >>= 1)
            tot += __shfl_xor_sync(0xffffffffu, tot, off);
        float a = __fdividef(e, tot);

        float u0 = g_u[node*ODIM + l], u1 = g_u[node*ODIM + 32 + l];
        const int4* ip4 = (const int4*)(g_idx + node*KNN);
        int4 i0 = ip4[0], i1 = ip4[1], i2 = ip4[2], i3 = ip4[3];
        int jj[16] = {i0.x,i0.y,i0.z,i0.w, i1.x,i1.y,i1.z,i1.w,
                      i2.x,i2.y,i2.z,i2.w, i3.x,i3.y,i3.z,i3.w};
        float acc0 = 0.f, acc1 = 0.f;
#pragma unroll
        for (int k = 0; k < KNN; ++k) {
            float ak = __shfl_sync(0xffffffffu, a, k);
            int j = jj[k];
            float v0 = g_v[j*ODIM + l], v1 = g_v[j*ODIM + 32 + l];
            float hn0 = silu_f(fmaf(u0 + v0, A0, B0));
            float hn1 = silu_f(fmaf(u1 + v1, A1, B1));
            acc0 = fmaf(ak, hn0, acc0);
            acc1 = fmaf(ak, hn1, acc1);
        }
        out[node*ODIM + l] = acc0;
        out[node*ODIM + 32 + l] = acc1;
    }
}

// ---------------- launch ----------------------------------------------------
extern "C" void kernel_launch(void* const* d_in, const int* in_sizes, int n_in,
                              void* d_out, int out_size) {
    const float* x   = (const float*)d_in[0];
    const float* W1  = (const float*)d_in[2];
    const float* b1  = (const float*)d_in[3];
    const float* g1  = (const float*)d_in[4];
    const float* be1 = (const float*)d_in[5];
    const float* Wg  = (const float*)d_in[6];
    const float* bg  = (const float*)d_in[7];
    const float* gg  = (const float*)d_in[8];
    const float* beg = (const float*)d_in[9];
    float* out = (float*)d_out;

    const int knn_smem = NPG*CDIM*4 + NPG*4 + KTH*BUFD*8
                       + 2*CDIM*ODIM*4 + ODIM*4;          // 213248 B
    cudaFuncSetAttribute(knn_kernel, cudaFuncAttributeMaxDynamicSharedMemorySize, knn_smem);

    knn_kernel<<<BGRAPH*(NPG/256), KTH, knn_smem>>>(x, W1, b1);  // 1 (knn + u/v)
    hstat_kernel<<<RB2, 256>>>(g1, be1);                         // 2 (+ BN finalize)
    gate_kernel<<<RB2, 256>>>(Wg, bg, gg, beg);                  // 3 (+ gate finalize)
    out_kernel<<<RB2, 256>>>(out);                               // 4 <- ncu capture
}